// round 11
// baseline (speedup 1.0000x reference)
#include <cuda_runtime.h>
#include <cuda_fp16.h>
#include <math.h>
#include <stdint.h>

// Problem dims (fixed): B=4, S=4096, DM=1024, H=16, HD=64
#define MDIM 16384   // B*S tokens
#define NDIM 1024
#define KDIM 1024

// ---------------------------------------------------------------------------
// Device scratch (no allocations allowed in kernel_launch)
// ---------------------------------------------------------------------------
__device__ __half g_xh[(size_t)MDIM * KDIM];     // x (fp16)
__device__ __half g_wh[4ull * NDIM * KDIM];      // [Wq|Wk|Wv|Wfc] (fp16)
__device__ float  g_QKV[3ull * MDIM * NDIM];     // fp32 Q|K|V
__device__ __half g_ah[(size_t)MDIM * NDIM];     // attn out (fp16)

// ---------------------------------------------------------------------------
// Generic-PTX tensor core helpers (legal on plain sm_103 target)
// ---------------------------------------------------------------------------
__device__ __forceinline__ uint32_t smem_to_u32(const void* p) {
    uint32_t a;
    asm("{ .reg .u64 t; cvta.to.shared.u64 t, %1; cvt.u32.u64 %0, t; }" : "=r"(a) : "l"(p));
    return a;
}

__device__ __forceinline__ void cp_async16(uint32_t dst, const void* src) {
    asm volatile("cp.async.cg.shared.global [%0], [%1], 16;" :: "r"(dst), "l"(src) : "memory");
}
#define CP_COMMIT() asm volatile("cp.async.commit_group;" ::: "memory")
#define CP_WAIT(n)  asm volatile("cp.async.wait_group %0;" :: "n"(n) : "memory")

#define LDSM_X4(r0, r1, r2, r3, addr) \
    asm volatile("ldmatrix.sync.aligned.m8n8.x4.shared.b16 {%0,%1,%2,%3}, [%4];" \
                 : "=r"(r0), "=r"(r1), "=r"(r2), "=r"(r3) : "r"(addr))

#define MMAF16(d, a, b0, b1) \
    asm volatile("mma.sync.aligned.m16n8k16.row.col.f32.f16.f16.f32 " \
                 "{%0,%1,%2,%3},{%4,%5,%6,%7},{%8,%9},{%0,%1,%2,%3};" \
                 : "+f"((d)[0]), "+f"((d)[1]), "+f"((d)[2]), "+f"((d)[3]) \
                 : "r"((a)[0]), "r"((a)[1]), "r"((a)[2]), "r"((a)[3]), \
                   "r"(b0), "r"(b1))

// ---------------------------------------------------------------------------
// fp16 GEMM: C[m,n] = sum_k A[m,k] * B[n,k]   (both K-contiguous, fp32 accum)
// 128x128x32 tile, 256 threads, 8 warps (4m x 2n), warp tile 32m x 64n.
// 3-stage cp.async pipeline, ONE barrier per chunk, 2 CTAs/SM.
// ---------------------------------------------------------------------------
#define ROWB 80                                   // padded row bytes (40 fp16)
#define TILE_BYTES (128 * ROWB)                   // 10240
#define STAGE_BYTES (2 * TILE_BYTES)              // 20480 (A, B)
#define NSTAGE 3
#define SMEM_DYN_BYTES (NSTAGE * STAGE_BYTES)     // 61440
#define OFF_A 0
#define OFF_B TILE_BYTES
#define NCHUNK (KDIM / 32)                        // 32

__device__ __forceinline__ void stage_load(
    uint32_t sb, const __half* Ap, const __half* Bp, int k0)
{
    const int tid = threadIdx.x;
    const int row = tid >> 1;
    const int half_ = tid & 1;                    // 0 or 1 -> 32B each
    const uint32_t soff = (uint32_t)row * ROWB + half_ * 32;
    const size_t goff = (size_t)row * KDIM + half_ * 16 + k0;
    cp_async16(sb + OFF_A + soff,      Ap + goff);
    cp_async16(sb + OFF_A + soff + 16, Ap + goff + 8);
    cp_async16(sb + OFF_B + soff,      Bp + goff);
    cp_async16(sb + OFF_B + soff + 16, Bp + goff + 8);
    CP_COMMIT();
}

__device__ void gemm_fp16(const __half* __restrict__ A,
                          const __half* __restrict__ B,
                          float* __restrict__ C)
{
    extern __shared__ char smem_raw[];
    const uint32_t base = smem_to_u32(smem_raw);

    const int tid = threadIdx.x;
    const int wid = tid >> 5;
    const int lane = tid & 31;
    const int warp_m = (wid & 3) * 32;            // 0,32,64,96
    const int warp_n = (wid >> 2) * 64;           // 0,64
    const int mBase = blockIdx.y * 128;
    const int nBase = blockIdx.x * 128;

    const __half* Ap = A + (size_t)mBase * KDIM;
    const __half* Bp = B + (size_t)nBase * KDIM;

    // ldmatrix per-lane relative offsets (within a tile), k-half via (lane>>4)
    uint32_t a_off[2], b_off[4];
#pragma unroll
    for (int i = 0; i < 2; i++)
        a_off[i] = (uint32_t)(warp_m + i * 16 + (lane & 15)) * ROWB + ((lane >> 4) << 4);
#pragma unroll
    for (int jj = 0; jj < 4; jj++)
        b_off[jj] = (uint32_t)(warp_n + jj * 16 + (lane & 15)) * ROWB + ((lane >> 4) << 4);

    float acc[2][8][4];
#pragma unroll
    for (int i = 0; i < 2; i++)
#pragma unroll
        for (int j = 0; j < 8; j++)
#pragma unroll
            for (int q = 0; q < 4; q++) acc[i][j][q] = 0.0f;

    stage_load(base,               Ap, Bp, 0);
    stage_load(base + STAGE_BYTES, Ap, Bp, 32);

    int rd_stage = 0, wr_stage = 2;

#pragma unroll 1
    for (int c = 0; c < NCHUNK; c++) {
        // pending groups at this point: {c, c+1} -> wait leaves at most 1
        if (c < NCHUNK - 1) { CP_WAIT(1); } else { CP_WAIT(0); }
        __syncthreads();

        const uint32_t sb = base + rd_stage * STAGE_BYTES;
        rd_stage = (rd_stage == NSTAGE - 1) ? 0 : rd_stage + 1;

#pragma unroll
        for (int kk = 0; kk < 2; kk++) {
            const uint32_t ko = kk * 32;          // 16 fp16 = 32 bytes
            uint32_t ah[2][4];
#pragma unroll
            for (int i = 0; i < 2; i++)
                LDSM_X4(ah[i][0], ah[i][1], ah[i][2], ah[i][3], sb + OFF_A + a_off[i] + ko);
            uint32_t bh[4][4];
#pragma unroll
            for (int jj = 0; jj < 4; jj++)
                LDSM_X4(bh[jj][0], bh[jj][1], bh[jj][2], bh[jj][3], sb + OFF_B + b_off[jj] + ko);

#pragma unroll
            for (int i = 0; i < 2; i++)
#pragma unroll
                for (int jj = 0; jj < 4; jj++) {
                    MMAF16(acc[i][2 * jj],     ah[i], bh[jj][0], bh[jj][2]);
                    MMAF16(acc[i][2 * jj + 1], ah[i], bh[jj][1], bh[jj][3]);
                }
        }

        // stage wr_stage was last read in iteration c-1 (protected by the
        // barrier above); safe to overwrite without a second barrier.
        if (c + 2 < NCHUNK) {
            stage_load(base + wr_stage * STAGE_BYTES, Ap, Bp, (c + 2) * 32);
            wr_stage = (wr_stage == NSTAGE - 1) ? 0 : wr_stage + 1;
        }
    }

    // epilogue: fp32 store
#pragma unroll
    for (int i = 0; i < 2; i++) {
        const int r0 = mBase + warp_m + i * 16 + (lane >> 2);
#pragma unroll
        for (int j = 0; j < 8; j++) {
            const int col = nBase + warp_n + j * 8 + (lane & 3) * 2;
            *(float2*)(C + (size_t)r0 * NDIM + col) =
                make_float2(acc[i][j][0], acc[i][j][1]);
            *(float2*)(C + (size_t)(r0 + 8) * NDIM + col) =
                make_float2(acc[i][j][2], acc[i][j][3]);
        }
    }
}

__global__ void __launch_bounds__(256, 2)
qkv_mm_kernel()
{
    const int z = blockIdx.z;
    gemm_fp16(g_xh,
              g_wh + (size_t)z * NDIM * KDIM,
              g_QKV + (size_t)z * MDIM * NDIM);
}

__global__ void __launch_bounds__(256, 2)
fc_mm_kernel(float* __restrict__ out)
{
    gemm_fp16(g_ah, g_wh + 3ull * NDIM * KDIM, out);
}

// ---------------------------------------------------------------------------
// fp32 -> fp16 conversion, all 5 tensors in one launch
// ---------------------------------------------------------------------------
#define NX4 ((long)MDIM * KDIM / 4)               // x float4 count (4M)
#define NW4 ((long)NDIM * KDIM / 4)               // per-W float4 count (256K)
#define NCVT4 (NX4 + 4 * NW4)

__global__ void __launch_bounds__(256)
cvt_all_kernel(const float* __restrict__ x,  const float* __restrict__ wq,
               const float* __restrict__ wk, const float* __restrict__ wv,
               const float* __restrict__ wfc)
{
    const long i = (long)blockIdx.x * 256 + threadIdx.x;
    if (i >= NCVT4) return;
    const float* src;
    __half2* dst;
    long j;
    if (i < NX4) {
        src = x; j = i; dst = (__half2*)g_xh;
    } else {
        const long r = i - NX4;
        const int w = (int)(r >> 18);             // NW4 = 2^18
        j = r & (NW4 - 1);
        src = (w == 0) ? wq : (w == 1) ? wk : (w == 2) ? wv : wfc;
        dst = (__half2*)(g_wh + (size_t)w * NDIM * KDIM);
    }
    float4 v = ((const float4*)src)[j];
    dst[2 * j]     = __half2(__float2half_rn(v.x), __float2half_rn(v.y));
    dst[2 * j + 1] = __half2(__float2half_rn(v.z), __float2half_rn(v.w));
}

// ---------------------------------------------------------------------------
// Per-token attention over the heads axis (16x16 per token).
// 128 threads / block, 8 tokens / block, K & V staged in smem (64 KB);
// head-group reads become LDS broadcasts.
// ---------------------------------------------------------------------------
#define ATOK 8
#define ATTN_SMEM (2 * ATOK * 1024 * 4)           // 65536

__global__ void __launch_bounds__(128)
attn_kernel()
{
    extern __shared__ float sbuf[];               // [K | V], each ATOK*1024 floats
    float4* sK4 = (float4*)sbuf;
    float4* sV4 = (float4*)(sbuf + ATOK * 1024);

    const int tid = threadIdx.x;
    const int token0 = blockIdx.x * ATOK;

    const float4* Kg = (const float4*)(g_QKV + (size_t)MDIM * NDIM) + (size_t)token0 * 256;
    const float4* Vg = (const float4*)(g_QKV + 2ull * MDIM * NDIM) + (size_t)token0 * 256;
#pragma unroll
    for (int i = 0; i < (ATOK * 256) / 128; i++) {
        sK4[tid + i * 128] = Kg[tid + i * 128];
        sV4[tid + i * 128] = Vg[tid + i * 128];
    }
    __syncthreads();

    const int lt = tid >> 4;
    const int h = tid & 15;
    const int token = token0 + lt;

    const float4* Q4 = (const float4*)(g_QKV) + (size_t)token * 256 + h * 16;
    const float4* K4 = sK4 + lt * 256;
    const float4* V4 = sV4 + lt * 256;

    float4 q[16];
#pragma unroll
    for (int i = 0; i < 16; i++) q[i] = Q4[i];

    float s[16];
#pragma unroll
    for (int t = 0; t < 16; t++) {
        float acc = 0.0f;
#pragma unroll
        for (int dd = 0; dd < 16; dd++) {
            float4 kv = K4[t * 16 + dd];
            acc = fmaf(q[dd].x, kv.x, acc);
            acc = fmaf(q[dd].y, kv.y, acc);
            acc = fmaf(q[dd].z, kv.z, acc);
            acc = fmaf(q[dd].w, kv.w, acc);
        }
        s[t] = acc * 0.125f;
    }

    float mx = s[0];
#pragma unroll
    for (int t = 1; t < 16; t++) mx = fmaxf(mx, s[t]);
    float sum = 0.0f;
#pragma unroll
    for (int t = 0; t < 16; t++) { s[t] = expf(s[t] - mx); sum += s[t]; }
    const float inv = 1.0f / sum;

    float4 o[16];
#pragma unroll
    for (int i = 0; i < 16; i++) o[i] = make_float4(0.f, 0.f, 0.f, 0.f);
#pragma unroll
    for (int t = 0; t < 16; t++) {
        const float p = s[t] * inv;
#pragma unroll
        for (int dd = 0; dd < 16; dd++) {
            float4 vv = V4[t * 16 + dd];
            o[dd].x = fmaf(p, vv.x, o[dd].x);
            o[dd].y = fmaf(p, vv.y, o[dd].y);
            o[dd].z = fmaf(p, vv.z, o[dd].z);
            o[dd].w = fmaf(p, vv.w, o[dd].w);
        }
    }

    const size_t obase = (size_t)token * NDIM + h * 64;
    __half2* OH = (__half2*)(g_ah + obase);
#pragma unroll
    for (int i = 0; i < 16; i++) {
        OH[2 * i]     = __half2(__float2half_rn(o[i].x), __float2half_rn(o[i].y));
        OH[2 * i + 1] = __half2(__float2half_rn(o[i].z), __float2half_rn(o[i].w));
    }
}

// ---------------------------------------------------------------------------
extern "C" void kernel_launch(void* const* d_in, const int* in_sizes, int n_in,
                              void* d_out, int out_size)
{
    const float* x   = (const float*)d_in[0];
    const float* Wq  = (const float*)d_in[1];
    const float* Wk  = (const float*)d_in[2];
    const float* Wv  = (const float*)d_in[3];
    const float* Wfc = (const float*)d_in[4];
    float* out = (float*)d_out;

    cudaFuncSetAttribute(qkv_mm_kernel, cudaFuncAttributeMaxDynamicSharedMemorySize, SMEM_DYN_BYTES);
    cudaFuncSetAttribute(fc_mm_kernel,  cudaFuncAttributeMaxDynamicSharedMemorySize, SMEM_DYN_BYTES);
    cudaFuncSetAttribute(attn_kernel,   cudaFuncAttributeMaxDynamicSharedMemorySize, ATTN_SMEM);

    {
        const long nblk = (NCVT4 + 255) / 256;
        cvt_all_kernel<<<(unsigned)nblk, 256>>>(x, Wq, Wk, Wv, Wfc);
    }

    dim3 gQKV(NDIM / 128, MDIM / 128, 3);
    qkv_mm_kernel<<<gQKV, 256, SMEM_DYN_BYTES>>>();

    attn_kernel<<<MDIM / ATOK, 128, ATTN_SMEM>>>();

    dim3 gFC(NDIM / 128, MDIM / 128, 1);
    fc_mm_kernel<<<gFC, 256, SMEM_DYN_BYTES>>>(out);
}